// round 3
// baseline (speedup 1.0000x reference)
#include <cuda_runtime.h>
#include <cstdint>

// Problem-fixed sizes (N=100000, E=1600000, F: 128 -> 128 -> 64)
#define NMAX 100000

// Scratch (static __device__ arrays; no allocation APIs allowed)
__device__ float    g_S2[NMAX * 128];   // spmm1 accumulator
__device__ float    g_S1[NMAX * 64];    // z = dropout(relu(S2@W1+b1)) @ W2
__device__ unsigned g_mask[NMAX * 4];   // packed keep bits, 128 per node

// ---------------------------------------------------------------------------
// Vector atomic reduction (sm_90+): 16B single L2 RMW transaction, no return.
__device__ __forceinline__ void red_add_v4(float4* p, float a, float b, float c, float d) {
    asm volatile("red.global.add.v4.f32 [%0], {%1,%2,%3,%4};"
                 :: "l"(p), "f"(a), "f"(b), "f"(c), "f"(d) : "memory");
}

// ---------------------------------------------------------------------------
// JAX threefry2x32 with key = (0, 42)
__device__ __forceinline__ uint2 tf2x32(unsigned c0, unsigned c1) {
    const unsigned ks0 = 0u, ks1 = 42u;
    const unsigned ks2 = ks0 ^ ks1 ^ 0x1BD11BDAu;
    unsigned x0 = c0 + ks0, x1 = c1 + ks1;
#define TFR(r) { x0 += x1; x1 = (x1 << (r)) | (x1 >> (32 - (r))); x1 ^= x0; }
    TFR(13) TFR(15) TFR(26) TFR(6)   x0 += ks1; x1 += ks2 + 1u;
    TFR(17) TFR(29) TFR(16) TFR(24)  x0 += ks2; x1 += ks0 + 2u;
    TFR(13) TFR(15) TFR(26) TFR(6)   x0 += ks0; x1 += ks1 + 3u;
    TFR(17) TFR(29) TFR(16) TFR(24)  x0 += ks1; x1 += ks2 + 4u;
    TFR(13) TFR(15) TFR(26) TFR(6)   x0 += ks2; x1 += ks0 + 5u;
#undef TFR
    return make_uint2(x0, x1);
}

// ---------------------------------------------------------------------------
__global__ __launch_bounds__(256) void zero_s2_kernel(int n4) {
    int i = blockIdx.x * blockDim.x + threadIdx.x;
    if (i < n4) ((float4*)g_S2)[i] = make_float4(0.f, 0.f, 0.f, 0.f);
}

// ---------------------------------------------------------------------------
// Combined kernel: spmm1 (L2-bound) + dropout mask (ALU-bound) + out=b2 init
// (streaming writes), interleaved by block role so pipes overlap on every SM.
//   blockIdx % 6 == 0  -> aux block (first 625: mask, next 625: init)
//   otherwise          -> spmm edge block (256 edges)
#define AUX_SPLIT   625
#define AUX_STRIDE  (AUX_SPLIT * 256)

__global__ __launch_bounds__(256) void combo_kernel(const float4* __restrict__ x4,
                                                    const float* __restrict__ ew,
                                                    const int* __restrict__ src,
                                                    const int* __restrict__ dst, int E,
                                                    const float4* __restrict__ b2f4,
                                                    float4* __restrict__ out4, int nout4,
                                                    int nwords) {
    int b = blockIdx.x;
    int tid = threadIdx.x;

    if (b % 6 == 0) {
        int aux = b / 6;
        if (aux < AUX_SPLIT) {
            // Dropout keep-mask: JAX partitionable threefry. Element i uses
            // tf2x32(0, i); bits = y0^y1; keep iff MSB==0  (u<0.5 <=> bits<2^31).
            for (int t = aux * 256 + tid; t < nwords; t += AUX_STRIDE) {
                unsigned base = (unsigned)t * 32u;
                unsigned w = 0u;
#pragma unroll 8
                for (int j = 0; j < 32; ++j) {
                    uint2 y = tf2x32(0u, base + j);
                    w |= ((~(y.x ^ y.y)) >> 31) << j;
                }
                g_mask[t] = w;
            }
        } else {
            // d_out = b2 broadcast (layer-2 bias folded into init; spmm2
            // accumulates on top). Stride is a multiple of 16 float4s, so the
            // b2 element for a given thread is loop-invariant.
            int a2 = aux - AUX_SPLIT;
            int i0 = a2 * 256 + tid;
            float4 bv = __ldg(b2f4 + (i0 & 15));
            for (int i = i0; i < nout4; i += AUX_STRIDE) out4[i] = bv;
        }
        return;
    }

    // spmm1: S2[dst] += w * x[src]  (128 feats; 1 warp per edge per iteration)
    int sb = b - (b / 6) - 1;                 // dense spmm block id
    float4* acc4 = (float4*)g_S2;
    int lane = tid & 31;
    int e0 = sb * 256 + (tid >> 5) * 32;
    if (e0 >= E) return;
    int e = e0 + lane;
    int s = 0, d = 0; float w = 0.f;
    if (e < E) { s = __ldg(&src[e]); d = __ldg(&dst[e]); w = __ldg(&ew[e]); }

    int s0 = __shfl_sync(0xffffffffu, s, 0);
    float4 v = __ldg(&x4[(size_t)s0 * 32 + lane]);
#pragma unroll 4
    for (int j = 0; j < 32; ++j) {
        int   dj = __shfl_sync(0xffffffffu, d, j);
        float wj = __shfl_sync(0xffffffffu, w, j);
        float4 cur = v;
        if (j < 31) {
            int sn = __shfl_sync(0xffffffffu, s, j + 1);
            v = __ldg(&x4[(size_t)sn * 32 + lane]);
        }
        red_add_v4(&acc4[(size_t)dj * 32 + lane], cur.x * wj, cur.y * wj, cur.z * wj, cur.w * wj);
    }
}

// spmm2: d_out[dst] += w * z[src]  (64 feats; half-warp per edge, 2 edges/iter)
__global__ __launch_bounds__(256) void spmm64_kernel(const float* __restrict__ ew,
                                                     const int* __restrict__ src,
                                                     const int* __restrict__ dst,
                                                     float4* __restrict__ out4, int E) {
    const float4* h4 = (const float4*)g_S1;
    int lane = threadIdx.x & 31;
    long warp = ((long)blockIdx.x * blockDim.x + threadIdx.x) >> 5;
    int e0 = (int)(warp * 32);
    if (e0 >= E) return;
    int e = e0 + lane;
    int s = 0, d = 0; float w = 0.f;
    if (e < E) { s = __ldg(&src[e]); d = __ldg(&dst[e]); w = __ldg(&ew[e]); }
    int half = lane >> 4, fl = lane & 15;
#pragma unroll 4
    for (int j = 0; j < 16; ++j) {
        int me = 2 * j + half;
        int   sj = __shfl_sync(0xffffffffu, s, me);
        int   dj = __shfl_sync(0xffffffffu, d, me);
        float wj = __shfl_sync(0xffffffffu, w, me);
        float4 v = __ldg(&h4[(size_t)sj * 16 + fl]);
        red_add_v4(&out4[(size_t)dj * 16 + fl], v.x * wj, v.y * wj, v.z * wj, v.w * wj);
    }
}

// ---------------------------------------------------------------------------
// Fused: z = (dropout(relu(S2 @ W1 + b1))) @ W2  -> g_S1.
// Block = 64 rows. W1 (64KB) in smem stage 1; W2 (padded 128x68) overlays it
// for stage 2; H tile (64 x 129) lives above.
#define RB     64
#define HPAD   129
#define W2PAD  68
#define FUSED_SMEM ((16384 + RB * HPAD) * 4)

__device__ __forceinline__ float f4get(const float4& v, int k) {
    switch (k) { case 0: return v.x; case 1: return v.y; case 2: return v.z; default: return v.w; }
}
__device__ __forceinline__ void fma4(float* a, float xs, float4 w) {
    a[0] += xs * w.x; a[1] += xs * w.y; a[2] += xs * w.z; a[3] += xs * w.w;
}

__global__ __launch_bounds__(256) void fused_kernel(const float* __restrict__ b1,
                                                    const float* __restrict__ W1,
                                                    const float* __restrict__ W2, int n) {
    extern __shared__ float sm[];
    float* W1s = sm;            // 128x128 (stage 1)
    float* W2s = sm;            // 128x68 padded, overlays W1s (stage 2)
    float* Hs  = sm + 16384;    // RB x HPAD

    int tid = threadIdx.x;
    {   // load W1 (4096 float4)
        float4* d4 = (float4*)W1s;
        const float4* s4 = (const float4*)W1;
#pragma unroll
        for (int i = 0; i < 16; ++i) d4[tid + i * 256] = s4[tid + i * 256];
    }
    __syncthreads();

    int cg = tid & 7;            // column group: cols [cg*16, cg*16+16)
    int rg = tid >> 3;           // row group: rows rg*2, rg*2+1
    int c0 = cg * 16;
    int rot1 = cg >> 1;          // stage-1 bank-derotation
    int row0 = blockIdx.x * RB + rg * 2;
    bool ok0 = (row0 < n), ok1 = (row0 + 1 < n);

    float acc[2][16];
#pragma unroll
    for (int i = 0; i < 2; ++i)
#pragma unroll
        for (int j = 0; j < 16; ++j) acc[i][j] = 0.f;

    const float4* r0p = ((const float4*)g_S2) + (size_t)row0 * 32;
    const float4* r1p = ((const float4*)g_S2) + (size_t)(row0 + 1) * 32;

    // Stage 1: acc = S2_rows @ W1.  Per-thread float4 reads of W1s are rotated
    // by r=(p+(cg>>1))&3 so warp banks are 16*(cg&1)+4r: conflict-free.
    for (int kk = 0; kk < 32; ++kk) {
        float4 xq0 = ok0 ? __ldg(r0p + kk) : make_float4(0.f, 0.f, 0.f, 0.f);
        float4 xq1 = ok1 ? __ldg(r1p + kk) : make_float4(0.f, 0.f, 0.f, 0.f);
#pragma unroll
        for (int q = 0; q < 4; ++q) {
            const float4* wrow = (const float4*)(W1s + (kk * 4 + q) * 128 + c0);
            float xs0 = f4get(xq0, q), xs1 = f4get(xq1, q);
#pragma unroll
            for (int p = 0; p < 4; ++p) {
                int r = (p + rot1) & 3;
                float4 wv = wrow[r];
                fma4(acc[0] + r * 4, xs0, wv);
                fma4(acc[1] + r * 4, xs1, wv);
            }
        }
    }

    // bias + relu + dropout (exact JAX partitionable-threefry mask) -> Hs
    {
        float barr[16];
        float4 t0 = __ldg((const float4*)(b1 + c0));
        float4 t1 = __ldg((const float4*)(b1 + c0 + 4));
        float4 t2 = __ldg((const float4*)(b1 + c0 + 8));
        float4 t3 = __ldg((const float4*)(b1 + c0 + 12));
        barr[0]=t0.x; barr[1]=t0.y; barr[2]=t0.z; barr[3]=t0.w;
        barr[4]=t1.x; barr[5]=t1.y; barr[6]=t1.z; barr[7]=t1.w;
        barr[8]=t2.x; barr[9]=t2.y; barr[10]=t2.z; barr[11]=t2.w;
        barr[12]=t3.x; barr[13]=t3.y; barr[14]=t3.z; barr[15]=t3.w;

        unsigned m0 = ok0 ? g_mask[row0 * 4 + (cg >> 1)] : 0u;
        unsigned m1 = ok1 ? g_mask[(row0 + 1) * 4 + (cg >> 1)] : 0u;
        int sh = (cg & 1) * 16;
        float* h0 = Hs + (rg * 2 + 0) * HPAD + c0;
        float* h1 = Hs + (rg * 2 + 1) * HPAD + c0;
#pragma unroll
        for (int j = 0; j < 16; ++j) {
            float a0 = fmaxf(acc[0][j] + barr[j], 0.f);
            float a1 = fmaxf(acc[1][j] + barr[j], 0.f);
            h0[j] = ((m0 >> (sh + j)) & 1u) ? a0 * 2.f : 0.f;  // /(1-p), p=0.5
            h1[j] = ((m1 >> (sh + j)) & 1u) ? a1 * 2.f : 0.f;
        }
    }
    __syncthreads();

    {   // overlay-load W2 into padded 128x68 layout
        const float4* s4 = (const float4*)W2;
#pragma unroll
        for (int i = 0; i < 8; ++i) {
            int idx = tid + i * 256;          // 0..2047 float4s
            int row = idx >> 4, c4 = idx & 15;
            ((float4*)(W2s + row * W2PAD))[c4] = s4[idx];
        }
    }
    __syncthreads();

    // Stage 2: z = Hs @ W2. Row stride 68 + per-(cg>=4) k-rotation of 1 makes
    // warp banks (4k + 8cg) mod 32 all distinct: conflict-free.
    float z0[8], z1[8];
#pragma unroll
    for (int j = 0; j < 8; ++j) { z0[j] = 0.f; z1[j] = 0.f; }
    const float* h0p = Hs + (rg * 2 + 0) * HPAD;
    const float* h1p = Hs + (rg * 2 + 1) * HPAD;
    int krot = cg >> 2;                        // 0 or 1
#pragma unroll 4
    for (int kk = 0; kk < 128; ++kk) {
        int k = (kk + krot) & 127;
        const float* wp = W2s + k * W2PAD + cg * 8;
        float4 wa = *(const float4*)(wp);
        float4 wb = *(const float4*)(wp + 4);
        float ha = h0p[k], hb = h1p[k];
        z0[0]+=ha*wa.x; z0[1]+=ha*wa.y; z0[2]+=ha*wa.z; z0[3]+=ha*wa.w;
        z0[4]+=ha*wb.x; z0[5]+=ha*wb.y; z0[6]+=ha*wb.z; z0[7]+=ha*wb.w;
        z1[0]+=hb*wa.x; z1[1]+=hb*wa.y; z1[2]+=hb*wa.z; z1[3]+=hb*wa.w;
        z1[4]+=hb*wb.x; z1[5]+=hb*wb.y; z1[6]+=hb*wb.z; z1[7]+=hb*wb.w;
    }
    if (ok0) {
        float4* o = (float4*)(g_S1 + (size_t)row0 * 64 + cg * 8);
        o[0] = make_float4(z0[0], z0[1], z0[2], z0[3]);
        o[1] = make_float4(z0[4], z0[5], z0[6], z0[7]);
    }
    if (ok1) {
        float4* o = (float4*)(g_S1 + (size_t)(row0 + 1) * 64 + cg * 8);
        o[0] = make_float4(z1[0], z1[1], z1[2], z1[3]);
        o[1] = make_float4(z1[4], z1[5], z1[6], z1[7]);
    }
}

// ---------------------------------------------------------------------------
extern "C" void kernel_launch(void* const* d_in, const int* in_sizes, int n_in,
                              void* d_out, int out_size) {
    const float* x  = (const float*)d_in[0];
    const float* ew = (const float*)d_in[1];
    const float* W1 = (const float*)d_in[2];
    const float* b1 = (const float*)d_in[3];
    const float* W2 = (const float*)d_in[4];
    const float* b2 = (const float*)d_in[5];
    const int*  src = (const int*)d_in[6];
    const int*  dst = (const int*)d_in[7];
    (void)n_in; (void)out_size;

    int N = in_sizes[0] / 128;
    int E = in_sizes[1];

    cudaFuncSetAttribute(fused_kernel, cudaFuncAttributeMaxDynamicSharedMemorySize, FUSED_SMEM);

    // 1) zero layer-1 accumulator (must complete before spmm1 atomics)
    int n4 = N * 32;
    zero_s2_kernel<<<(n4 + 255) / 256, 256>>>(n4);

    // 2) combo: spmm1 + dropout mask + out-init, role-interleaved (1 aux per 6)
    int spmmBlocks = (E + 255) / 256;                 // 6250
    int auxBlocks  = 2 * AUX_SPLIT;                   // 1250 (mask 625, init 625)
    int total      = spmmBlocks + auxBlocks;          // aux = every 6th block
    combo_kernel<<<total, 256>>>((const float4*)x, ew, src, dst, E,
                                 (const float4*)b2, (float4*)d_out, N * 16, N * 4);

    // 3) fused: S1 = dropout(relu(S2@W1+b1)) @ W2
    fused_kernel<<<(N + RB - 1) / RB, 256, FUSED_SMEM>>>(b1, W1, W2, N);

    // 4) spmm2: d_out += A @ S1
    spmm64_kernel<<<(E + 255) / 256, 256>>>(ew, src, dst, (float4*)d_out, E);
}

// round 4
// speedup vs baseline: 5.7850x; 5.7850x over previous
#include <cuda_runtime.h>
#include <cstdint>

// Problem-fixed sizes (N=100000, E=1600000, F: 128 -> 128 -> 64)
#define NMAX 100000

// Scratch (static __device__ arrays; no allocation APIs allowed)
__device__ float    g_S2[NMAX * 128];   // spmm1 accumulator
__device__ float    g_S1[NMAX * 64];    // z = dropout(relu(S2@W1+b1)) @ W2
__device__ unsigned g_mask[NMAX * 4];   // packed keep bits, 128 per node

// ---------------------------------------------------------------------------
// Vector atomic reduction (sm_90+): 16B single L2 RMW transaction, no return.
__device__ __forceinline__ void red_add_v4(float4* p, float a, float b, float c, float d) {
    asm volatile("red.global.add.v4.f32 [%0], {%1,%2,%3,%4};"
                 :: "l"(p), "f"(a), "f"(b), "f"(c), "f"(d) : "memory");
}

// ---------------------------------------------------------------------------
// JAX threefry2x32 with key = (0, 42)
__device__ __forceinline__ uint2 tf2x32(unsigned c0, unsigned c1) {
    const unsigned ks0 = 0u, ks1 = 42u;
    const unsigned ks2 = ks0 ^ ks1 ^ 0x1BD11BDAu;
    unsigned x0 = c0 + ks0, x1 = c1 + ks1;
#define TFR(r) { x0 += x1; x1 = (x1 << (r)) | (x1 >> (32 - (r))); x1 ^= x0; }
    TFR(13) TFR(15) TFR(26) TFR(6)   x0 += ks1; x1 += ks2 + 1u;
    TFR(17) TFR(29) TFR(16) TFR(24)  x0 += ks2; x1 += ks0 + 2u;
    TFR(13) TFR(15) TFR(26) TFR(6)   x0 += ks0; x1 += ks1 + 3u;
    TFR(17) TFR(29) TFR(16) TFR(24)  x0 += ks1; x1 += ks2 + 4u;
    TFR(13) TFR(15) TFR(26) TFR(6)   x0 += ks2; x1 += ks0 + 5u;
#undef TFR
    return make_uint2(x0, x1);
}

// ---------------------------------------------------------------------------
__global__ __launch_bounds__(256) void zero_s2_kernel(int n4) {
    int i = blockIdx.x * blockDim.x + threadIdx.x;
    if (i < n4) ((float4*)g_S2)[i] = make_float4(0.f, 0.f, 0.f, 0.f);
}

// ---------------------------------------------------------------------------
// Combined kernel: spmm1 (L2-bound) + dropout mask (ALU-bound) + out=b2 init
// (streaming writes), interleaved by block role so pipes overlap on every SM.
//   blockIdx % 6 == 0  -> aux block (first 625: mask, next 625: init)
//   otherwise          -> spmm edge block (256 edges)
#define AUX_SPLIT   625
#define AUX_STRIDE  (AUX_SPLIT * 256)

__global__ __launch_bounds__(256) void combo_kernel(const float4* __restrict__ x4,
                                                    const float* __restrict__ ew,
                                                    const int* __restrict__ src,
                                                    const int* __restrict__ dst, int E,
                                                    const float4* __restrict__ b2f4,
                                                    float4* __restrict__ out4, int nout4,
                                                    int nwords) {
    int b = blockIdx.x;
    int tid = threadIdx.x;

    if (b % 6 == 0) {
        int aux = b / 6;
        if (aux < AUX_SPLIT) {
            // Dropout keep-mask: JAX partitionable threefry. Element i uses
            // tf2x32(0, i); bits = y0^y1; keep iff MSB==0  (u<0.5 <=> bits<2^31).
            for (int t = aux * 256 + tid; t < nwords; t += AUX_STRIDE) {
                unsigned base = (unsigned)t * 32u;
                unsigned w = 0u;
#pragma unroll 8
                for (int j = 0; j < 32; ++j) {
                    uint2 y = tf2x32(0u, base + j);
                    w |= ((~(y.x ^ y.y)) >> 31) << j;
                }
                g_mask[t] = w;
            }
        } else {
            // d_out = b2 broadcast (layer-2 bias folded into init; spmm2
            // accumulates on top). Stride is a multiple of 16 float4s, so the
            // b2 element for a given thread is loop-invariant.
            int a2 = aux - AUX_SPLIT;
            int i0 = a2 * 256 + tid;
            float4 bv = __ldg(b2f4 + (i0 & 15));
            for (int i = i0; i < nout4; i += AUX_STRIDE) out4[i] = bv;
        }
        return;
    }

    // spmm1: S2[dst] += w * x[src]  (128 feats; 1 warp per edge per iteration)
    int sb = b - (b / 6) - 1;                 // dense spmm block id
    float4* acc4 = (float4*)g_S2;
    int lane = tid & 31;
    int e0 = sb * 256 + (tid >> 5) * 32;
    if (e0 >= E) return;
    int e = e0 + lane;
    int s = 0, d = 0; float w = 0.f;
    if (e < E) { s = __ldg(&src[e]); d = __ldg(&dst[e]); w = __ldg(&ew[e]); }

    int s0 = __shfl_sync(0xffffffffu, s, 0);
    float4 v = __ldg(&x4[(size_t)s0 * 32 + lane]);
#pragma unroll 4
    for (int j = 0; j < 32; ++j) {
        int   dj = __shfl_sync(0xffffffffu, d, j);
        float wj = __shfl_sync(0xffffffffu, w, j);
        float4 cur = v;
        if (j < 31) {
            int sn = __shfl_sync(0xffffffffu, s, j + 1);
            v = __ldg(&x4[(size_t)sn * 32 + lane]);
        }
        red_add_v4(&acc4[(size_t)dj * 32 + lane], cur.x * wj, cur.y * wj, cur.z * wj, cur.w * wj);
    }
}

// spmm2: d_out[dst] += w * z[src]  (64 feats; half-warp per edge, 2 edges/iter)
__global__ __launch_bounds__(256) void spmm64_kernel(const float* __restrict__ ew,
                                                     const int* __restrict__ src,
                                                     const int* __restrict__ dst,
                                                     float4* __restrict__ out4, int E) {
    const float4* h4 = (const float4*)g_S1;
    int lane = threadIdx.x & 31;
    long warp = ((long)blockIdx.x * blockDim.x + threadIdx.x) >> 5;
    int e0 = (int)(warp * 32);
    if (e0 >= E) return;
    int e = e0 + lane;
    int s = 0, d = 0; float w = 0.f;
    if (e < E) { s = __ldg(&src[e]); d = __ldg(&dst[e]); w = __ldg(&ew[e]); }
    int half = lane >> 4, fl = lane & 15;
#pragma unroll 4
    for (int j = 0; j < 16; ++j) {
        int me = 2 * j + half;
        int   sj = __shfl_sync(0xffffffffu, s, me);
        int   dj = __shfl_sync(0xffffffffu, d, me);
        float wj = __shfl_sync(0xffffffffu, w, me);
        float4 v = __ldg(&h4[(size_t)sj * 16 + fl]);
        red_add_v4(&out4[(size_t)dj * 16 + fl], v.x * wj, v.y * wj, v.z * wj, v.w * wj);
    }
}

// ---------------------------------------------------------------------------
// Fused: z = (dropout(relu(S2 @ W1 + b1))) @ W2  -> g_S1.
// Block = 64 rows. W1 (64KB) in smem stage 1; W2 (padded 128x68) overlays it
// for stage 2; H tile (64 x 129) lives above.
// NOTE: all register-accumulator indices are compile-time constants (the R3
// dynamic-rotation variant forced acc[] into local memory -> 5x regression).
#define RB     64
#define HPAD   129
#define W2PAD  68
#define FUSED_SMEM ((16384 + RB * HPAD) * 4)

__device__ __forceinline__ float f4get(const float4& v, int k) {
    switch (k) { case 0: return v.x; case 1: return v.y; case 2: return v.z; default: return v.w; }
}
__device__ __forceinline__ void fma16(float* a, float xs, float4 w0, float4 w1, float4 w2, float4 w3) {
    a[0]  += xs * w0.x; a[1]  += xs * w0.y; a[2]  += xs * w0.z; a[3]  += xs * w0.w;
    a[4]  += xs * w1.x; a[5]  += xs * w1.y; a[6]  += xs * w1.z; a[7]  += xs * w1.w;
    a[8]  += xs * w2.x; a[9]  += xs * w2.y; a[10] += xs * w2.z; a[11] += xs * w2.w;
    a[12] += xs * w3.x; a[13] += xs * w3.y; a[14] += xs * w3.z; a[15] += xs * w3.w;
}

__global__ __launch_bounds__(256) void fused_kernel(const float* __restrict__ b1,
                                                    const float* __restrict__ W1,
                                                    const float* __restrict__ W2, int n) {
    extern __shared__ float sm[];
    float* W1s = sm;            // 128x128 (stage 1)
    float* W2s = sm;            // 128x68 padded, overlays W1s (stage 2)
    float* Hs  = sm + 16384;    // RB x HPAD

    int tid = threadIdx.x;
    {   // load W1 (4096 float4)
        float4* d4 = (float4*)W1s;
        const float4* s4 = (const float4*)W1;
#pragma unroll
        for (int i = 0; i < 16; ++i) d4[tid + i * 256] = s4[tid + i * 256];
    }
    __syncthreads();

    int cg = tid & 7;            // column group: cols [cg*16, cg*16+16)
    int rg = tid >> 3;           // row group: rows rg*2, rg*2+1
    int c0 = cg * 16;
    int row0 = blockIdx.x * RB + rg * 2;
    bool ok0 = (row0 < n), ok1 = (row0 + 1 < n);

    float acc[2][16];
#pragma unroll
    for (int i = 0; i < 2; ++i)
#pragma unroll
        for (int j = 0; j < 16; ++j) acc[i][j] = 0.f;

    const float4* r0p = ((const float4*)g_S2) + (size_t)row0 * 32;
    const float4* r1p = ((const float4*)g_S2) + (size_t)(row0 + 1) * 32;

    // Stage 1: acc = S2_rows @ W1 (static register indexing only)
    for (int kk = 0; kk < 32; ++kk) {
        float4 xq0 = ok0 ? __ldg(r0p + kk) : make_float4(0.f, 0.f, 0.f, 0.f);
        float4 xq1 = ok1 ? __ldg(r1p + kk) : make_float4(0.f, 0.f, 0.f, 0.f);
#pragma unroll
        for (int k4 = 0; k4 < 4; ++k4) {
            const float4* wr = (const float4*)(W1s + (kk * 4 + k4) * 128 + c0);
            float4 w0 = wr[0], w1 = wr[1], w2 = wr[2], w3 = wr[3];
            fma16(acc[0], f4get(xq0, k4), w0, w1, w2, w3);
            fma16(acc[1], f4get(xq1, k4), w0, w1, w2, w3);
        }
    }

    // bias + relu + dropout (exact JAX partitionable-threefry mask) -> Hs
    {
        float barr[16];
        float4 t0 = __ldg((const float4*)(b1 + c0));
        float4 t1 = __ldg((const float4*)(b1 + c0 + 4));
        float4 t2 = __ldg((const float4*)(b1 + c0 + 8));
        float4 t3 = __ldg((const float4*)(b1 + c0 + 12));
        barr[0]=t0.x; barr[1]=t0.y; barr[2]=t0.z; barr[3]=t0.w;
        barr[4]=t1.x; barr[5]=t1.y; barr[6]=t1.z; barr[7]=t1.w;
        barr[8]=t2.x; barr[9]=t2.y; barr[10]=t2.z; barr[11]=t2.w;
        barr[12]=t3.x; barr[13]=t3.y; barr[14]=t3.z; barr[15]=t3.w;

        unsigned m0 = ok0 ? g_mask[row0 * 4 + (cg >> 1)] : 0u;
        unsigned m1 = ok1 ? g_mask[(row0 + 1) * 4 + (cg >> 1)] : 0u;
        int sh = (cg & 1) * 16;
        float* h0 = Hs + (rg * 2 + 0) * HPAD + c0;
        float* h1 = Hs + (rg * 2 + 1) * HPAD + c0;
#pragma unroll
        for (int j = 0; j < 16; ++j) {
            float a0 = fmaxf(acc[0][j] + barr[j], 0.f);
            float a1 = fmaxf(acc[1][j] + barr[j], 0.f);
            h0[j] = ((m0 >> (sh + j)) & 1u) ? a0 * 2.f : 0.f;  // /(1-p), p=0.5
            h1[j] = ((m1 >> (sh + j)) & 1u) ? a1 * 2.f : 0.f;
        }
    }
    __syncthreads();

    {   // overlay-load W2 into padded 128x68 layout
        const float4* s4 = (const float4*)W2;
#pragma unroll
        for (int i = 0; i < 8; ++i) {
            int idx = tid + i * 256;          // 0..2047 float4s
            int row = idx >> 4, c4 = idx & 15;
            ((float4*)(W2s + row * W2PAD))[c4] = s4[idx];
        }
    }
    __syncthreads();

    // Stage 2: z = Hs @ W2. Row stride 68 + k-rotation for cg>=4 removes the
    // 2-way bank conflict; k only feeds *shared* addresses (spill-safe).
    float z0[8], z1[8];
#pragma unroll
    for (int j = 0; j < 8; ++j) { z0[j] = 0.f; z1[j] = 0.f; }
    const float* h0p = Hs + (rg * 2 + 0) * HPAD;
    const float* h1p = Hs + (rg * 2 + 1) * HPAD;
    int krot = cg >> 2;                        // 0 or 1
#pragma unroll 4
    for (int kk = 0; kk < 128; ++kk) {
        int k = (kk + krot) & 127;
        const float* wp = W2s + k * W2PAD + cg * 8;
        float4 wa = *(const float4*)(wp);
        float4 wb = *(const float4*)(wp + 4);
        float ha = h0p[k], hb = h1p[k];
        z0[0]+=ha*wa.x; z0[1]+=ha*wa.y; z0[2]+=ha*wa.z; z0[3]+=ha*wa.w;
        z0[4]+=ha*wb.x; z0[5]+=ha*wb.y; z0[6]+=ha*wb.z; z0[7]+=ha*wb.w;
        z1[0]+=hb*wa.x; z1[1]+=hb*wa.y; z1[2]+=hb*wa.z; z1[3]+=hb*wa.w;
        z1[4]+=hb*wb.x; z1[5]+=hb*wb.y; z1[6]+=hb*wb.z; z1[7]+=hb*wb.w;
    }
    if (ok0) {
        float4* o = (float4*)(g_S1 + (size_t)row0 * 64 + cg * 8);
        o[0] = make_float4(z0[0], z0[1], z0[2], z0[3]);
        o[1] = make_float4(z0[4], z0[5], z0[6], z0[7]);
    }
    if (ok1) {
        float4* o = (float4*)(g_S1 + (size_t)(row0 + 1) * 64 + cg * 8);
        o[0] = make_float4(z1[0], z1[1], z1[2], z1[3]);
        o[1] = make_float4(z1[4], z1[5], z1[6], z1[7]);
    }
}

// ---------------------------------------------------------------------------
extern "C" void kernel_launch(void* const* d_in, const int* in_sizes, int n_in,
                              void* d_out, int out_size) {
    const float* x  = (const float*)d_in[0];
    const float* ew = (const float*)d_in[1];
    const float* W1 = (const float*)d_in[2];
    const float* b1 = (const float*)d_in[3];
    const float* W2 = (const float*)d_in[4];
    const float* b2 = (const float*)d_in[5];
    const int*  src = (const int*)d_in[6];
    const int*  dst = (const int*)d_in[7];
    (void)n_in; (void)out_size;

    int N = in_sizes[0] / 128;
    int E = in_sizes[1];

    cudaFuncSetAttribute(fused_kernel, cudaFuncAttributeMaxDynamicSharedMemorySize, FUSED_SMEM);

    // 1) zero layer-1 accumulator (must complete before spmm1 atomics)
    int n4 = N * 32;
    zero_s2_kernel<<<(n4 + 255) / 256, 256>>>(n4);

    // 2) combo: spmm1 + dropout mask + out-init, role-interleaved (1 aux per 6)
    int spmmBlocks = (E + 255) / 256;                 // 6250
    int auxBlocks  = 2 * AUX_SPLIT;                   // 1250 (mask 625, init 625)
    int total      = spmmBlocks + auxBlocks;          // aux = every 6th block
    combo_kernel<<<total, 256>>>((const float4*)x, ew, src, dst, E,
                                 (const float4*)b2, (float4*)d_out, N * 16, N * 4);

    // 3) fused: S1 = dropout(relu(S2@W1+b1)) @ W2
    fused_kernel<<<(N + RB - 1) / RB, 256, FUSED_SMEM>>>(b1, W1, W2, N);

    // 4) spmm2: d_out += A @ S1
    spmm64_kernel<<<(E + 255) / 256, 256>>>(ew, src, dst, (float4*)d_out, E);
}